// round 13
// baseline (speedup 1.0000x reference)
#include <cuda_runtime.h>
#include <math.h>

#define M_GT  128
#define BLOCK 128
#define APT   4            // anchors per thread

// Per-GT best-anchor key: (iou_bits << 32) | (0xFFFFFFFF - anchor_idx).
// IoU >= 0 so float bits are order-preserving under unsigned max; ~idx makes
// the smaller anchor index win ties (matches jnp.argmax axis=0 tie-break).
// Zero-initialized at module load; fix_kernel re-zeros it after each use, so
// every kernel_launch invocation (and every graph replay) starts from 0.
__device__ unsigned long long g_gt_key[M_GT];

__device__ __forceinline__ unsigned long long pack_key(float iou, unsigned idx) {
    return (((unsigned long long)__float_as_uint(iou)) << 32) |
           (unsigned long long)(0xFFFFFFFFu - idx);
}

__device__ __forceinline__ void encode_write(float* __restrict__ out, int N,
                                             float4 a, float4 g, int i,
                                             bool pos, bool aligned4) {
    const float EPS = 1.1920929e-07f;  // jnp.finfo(float32).eps
    float ax = (a.x + a.z) * 0.5f;
    float ay = (a.y + a.w) * 0.5f;
    float aw = fmaxf(a.z - a.x, EPS);
    float ah = fmaxf(a.w - a.y, EPS);
    float gx = (g.x + g.z) * 0.5f;
    float gy = (g.y + g.w) * 0.5f;
    float dx = (gx - ax) / aw;
    float dy = (gy - ay) / ah;
    float dw = logf((g.z - g.x) / aw);
    float dh = logf((g.w - g.y) / ah);
    if (!pos) { dx = 0.0f; dy = 0.0f; dw = 0.0f; dh = 0.0f; }
    if (aligned4) {
        ((float4*)(out + N))[i] = make_float4(dx, dy, dw, dh);
    } else {
        float* r = out + N + 4 * i;
        r[0] = dx; r[1] = dy; r[2] = dw; r[3] = dh;
    }
}

__global__ void __launch_bounds__(BLOCK)
match_kernel(const float4* __restrict__ anchors,
             const float4* __restrict__ gts,
             const int* __restrict__ labels,
             float* __restrict__ out,
             int N, int M, int aligned4)
{
    __shared__ float4 sgt[M_GT];
    __shared__ float  sarea[M_GT];
    __shared__ int    slab[M_GT];

    int tid  = threadIdx.x;
    int lane = tid & 31;
    for (int j = tid; j < M; j += BLOCK) {
        float4 g = gts[j];
        sgt[j]   = g;
        sarea[j] = (g.z - g.x) * (g.w - g.y);
        slab[j]  = labels[j];
    }
    __syncthreads();

    int base = blockIdx.x * (BLOCK * APT);

    unsigned idx[APT];
    bool     act[APT];
    float4   a[APT];
    float    area[APT];
    // per-anchor argmax state (axis=1), division-free: best (inter, den) + j
    float    binter[APT], bden[APT];
    int      bj[APT];

    #pragma unroll
    for (int k = 0; k < APT; ++k) {
        idx[k]  = (unsigned)(base + k * BLOCK + tid);
        act[k]  = (idx[k] < (unsigned)N);
        a[k]    = anchors[act[k] ? idx[k] : 0];
        area[k] = (a[k].z - a[k].x) * (a[k].w - a[k].y);
        binter[k] = -1.0f;   // j=0 always wins the first compare (den > 0)
        bden[k]   = 1.0f;
        bj[k]     = 0;
    }

    // Global high-water mark: hi word of g_gt_key[j] = best iou bits so far.
    // __ldcg (L2) sees atomic updates from other blocks; staleness only means
    // extra tournaments, never missed winners (atomicMax is the authority).
    const unsigned* gk_hi = ((const unsigned*)g_gt_key) + 1;  // stride 2

    for (int j = 0; j < M; ++j) {
        float4 g  = sgt[j];
        float  sa = sarea[j];

        // lane's candidate for GT j: best over its APT anchors
        float    ti = 0.0f, td = 1.0f;
        unsigned tx = 0xFFFFFFFFu;

        #pragma unroll
        for (int k = 0; k < APT; ++k) {
            float lx = fmaxf(a[k].x, g.x);
            float ly = fmaxf(a[k].y, g.y);
            float rx = fminf(a[k].z, g.z);
            float ry = fminf(a[k].w, g.w);
            float w  = fmaxf(rx - lx, 0.0f);
            float h  = fmaxf(ry - ly, 0.0f);
            float inter    = w * h;
            float area_sum = area[k] + sa;      // reference eval order
            float den      = area_sum - inter;  // > 0 always
            if (!act[k]) inter = 0.0f;

            // per-anchor argmax (axis=1), strict '>' keeps first j
            if (inter * bden[k] > binter[k] * den) {
                binter[k] = inter; bden[k] = den; bj[k] = j;
            }
            // lane candidate (axis=0), strict '>' prefers smaller k = smaller idx
            if (inter * td > ti * den) {
                ti = inter; td = den; tx = idx[k];
            }
        }

        // Gate: can any lane possibly beat the global best for this GT?
        // iou >= hc  <=>  inter*(1+hc) >= hc*area_sum   (division-free).
        // Conservative margin => may admit losers, never filters a winner.
        float hi = __uint_as_float(__ldcg(gk_hi + 2 * j));
        float hc = hi * 0.9999f;
        bool  cand = (ti > 0.0f) && (fmaf(hc, ti, ti) >= hc * (ti + td));
        unsigned bal = __ballot_sync(0xFFFFFFFFu, cand);
        if (bal == 0u) continue;   // steady state after warm-up

        // warp tournament, division-free cross-mult compare; symmetric
        // products + idx tie-break => all lanes converge to one winner.
        #pragma unroll
        for (int off = 16; off; off >>= 1) {
            float    oi = __shfl_xor_sync(0xFFFFFFFFu, ti, off);
            float    od = __shfl_xor_sync(0xFFFFFFFFu, td, off);
            unsigned ox = __shfl_xor_sync(0xFFFFFFFFu, tx, off);
            float p_o = oi * td;
            float p_m = ti * od;
            bool take = (p_o > p_m) || ((p_o == p_m) && (ox < tx));
            if (take) { ti = oi; td = od; tx = ox; }
        }

        if (lane == 0 && ti > 0.0f) {
            float iou = __fdiv_rn(ti, td);     // exact, reference-rounded
            atomicMax(&g_gt_key[j], pack_key(iou, tx));
        }
    }

    bool al4 = (aligned4 != 0);
    #pragma unroll
    for (int k = 0; k < APT; ++k) {
        if (!act[k]) continue;
        float best = __fdiv_rn(binter[k], bden[k]);  // reference-rounded max IoU
        bool pos = (best >= 0.5f);
        bool neg = (best < 0.4f) && !pos;
        out[idx[k]] = (float)(pos ? slab[bj[k]] : (neg ? 0 : -1));
        encode_write(out, N, a[k], sgt[bj[k]], idx[k], pos, al4);
        out[5 * N + idx[k]] = pos ? 1.0f : 0.0f;
    }
}

// Force best-anchor-per-GT positive: one WARP per GT. Each lane scans 4 GT
// columns (j = lane*4..lane*4+3) of the winning anchor's IoU row,
// division-free; 5-step tournament (tie -> smaller j) finds that anchor's
// per-anchor argmax; lane 0 writes. Resets g_gt_key for the next replay.
// Several GTs sharing one best anchor write identical values => deterministic.
__global__ void fix_kernel(const float4* __restrict__ anchors,
                           const float4* __restrict__ gts,
                           const int* __restrict__ labels,
                           float* __restrict__ out,
                           int N, int M, int aligned4)
{
    int warp = threadIdx.x >> 5;
    int lane = threadIdx.x & 31;
    int gt   = blockIdx.x * 4 + warp;
    if (gt >= M_GT) return;

    unsigned long long key = (gt < M_GT) ? g_gt_key[gt] : 0ULL;
    if (lane == 0) g_gt_key[gt] = 0ULL;       // restore invariant
    if (gt >= M) return;

    // key==0 => all ious for this GT were 0; jnp.argmax of all-zero col = 0
    int aidx = (key == 0ULL) ? 0
             : (int)(0xFFFFFFFFu - (unsigned)(key & 0xFFFFFFFFULL));
    if (aidx < 0 || aidx >= N) return;

    float4 a = anchors[aidx];                 // broadcast load, all lanes same
    float area_a = (a.z - a.x) * (a.w - a.y);

    // lane scans j = lane*4 .. lane*4+3 (ascending => strict '>' keeps first j)
    float bi = -1.0f, bd = 1.0f;
    int   bj = lane * 4;
    #pragma unroll
    for (int kk = 0; kk < 4; ++kk) {
        int j = lane * 4 + kk;
        if (j >= M) break;
        float4 g = gts[j];
        float sa = (g.z - g.x) * (g.w - g.y);
        float lx = fmaxf(a.x, g.x);
        float ly = fmaxf(a.y, g.y);
        float rx = fminf(a.z, g.z);
        float ry = fminf(a.w, g.w);
        float w  = fmaxf(rx - lx, 0.0f);
        float h  = fmaxf(ry - ly, 0.0f);
        float inter = w * h;
        float den   = (area_a + sa) - inter;
        if (inter * bd > bi * den) { bi = inter; bd = den; bj = j; }
    }
    // lanes whose first j >= M keep bi=-1 (never win; M>=1 so lane 0 valid)

    #pragma unroll
    for (int off = 16; off; off >>= 1) {
        float oi = __shfl_xor_sync(0xFFFFFFFFu, bi, off);
        float od = __shfl_xor_sync(0xFFFFFFFFu, bd, off);
        int   oj = __shfl_xor_sync(0xFFFFFFFFu, bj, off);
        float p_o = oi * bd;
        float p_m = bi * od;
        bool take = (p_o > p_m) || ((p_o == p_m) && (oj < bj));
        if (take) { bi = oi; bd = od; bj = oj; }
    }

    if (lane == 0) {
        float4 g = gts[bj];
        out[aidx] = (float)labels[bj];
        encode_write(out, N, a, g, aidx, true, aligned4 != 0);
        out[5 * N + aidx] = 1.0f;
    }
}

extern "C" void kernel_launch(void* const* d_in, const int* in_sizes, int n_in,
                              void* d_out, int out_size)
{
    const float4* anchors = (const float4*)d_in[0];
    const float4* gts     = (const float4*)d_in[1];
    const int*    labels  = (const int*)d_in[2];
    float*        out     = (float*)d_out;

    int N = in_sizes[0] / 4;
    int M = in_sizes[2];
    if (M > M_GT) M = M_GT;
    int aligned4 = ((N & 3) == 0) ? 1 : 0;

    int blocks = (N + BLOCK * APT - 1) / (BLOCK * APT);
    match_kernel<<<blocks, BLOCK>>>(anchors, gts, labels, out, N, M, aligned4);
    fix_kernel<<<M_GT / 4, 128>>>(anchors, gts, labels, out, N, M, aligned4);
}

// round 14
// speedup vs baseline: 1.3295x; 1.3295x over previous
#include <cuda_runtime.h>
#include <math.h>

#define M_GT  128
#define BLOCK 128
#define APT   4            // anchors per thread

// Per-GT best-anchor key: (iou_bits << 32) | (0xFFFFFFFF - anchor_idx).
// IoU >= 0 so float bits are order-preserving under unsigned max; ~idx makes
// the smaller anchor index win ties (matches jnp.argmax axis=0 tie-break).
// Zero-initialized at module load; fix_kernel re-zeros it after each use, so
// every kernel_launch invocation (and every graph replay) starts from 0.
__device__ unsigned long long g_gt_key[M_GT];

__device__ __forceinline__ unsigned long long pack_key(float iou, unsigned idx) {
    return (((unsigned long long)__float_as_uint(iou)) << 32) |
           (unsigned long long)(0xFFFFFFFFu - idx);
}

__device__ __forceinline__ void encode_write(float* __restrict__ out, int N,
                                             float4 a, float4 g, int i,
                                             bool pos, bool aligned4) {
    const float EPS = 1.1920929e-07f;  // jnp.finfo(float32).eps
    float ax = (a.x + a.z) * 0.5f;
    float ay = (a.y + a.w) * 0.5f;
    float aw = fmaxf(a.z - a.x, EPS);
    float ah = fmaxf(a.w - a.y, EPS);
    float gx = (g.x + g.z) * 0.5f;
    float gy = (g.y + g.w) * 0.5f;
    float dx = (gx - ax) / aw;
    float dy = (gy - ay) / ah;
    float dw = logf((g.z - g.x) / aw);
    float dh = logf((g.w - g.y) / ah);
    if (!pos) { dx = 0.0f; dy = 0.0f; dw = 0.0f; dh = 0.0f; }
    if (aligned4) {
        ((float4*)(out + N))[i] = make_float4(dx, dy, dw, dh);
    } else {
        float* r = out + N + 4 * i;
        r[0] = dx; r[1] = dy; r[2] = dw; r[3] = dh;
    }
}

__global__ void __launch_bounds__(BLOCK)
match_kernel(const float4* __restrict__ anchors,
             const float4* __restrict__ gts,
             const int* __restrict__ labels,
             float* __restrict__ out,
             int N, int M, int aligned4)
{
    __shared__ float4 sgt[M_GT];
    __shared__ float  sarea[M_GT];
    __shared__ int    slab[M_GT];

    int tid  = threadIdx.x;
    int lane = tid & 31;
    for (int j = tid; j < M; j += BLOCK) {
        float4 g = gts[j];
        sgt[j]   = g;
        sarea[j] = (g.z - g.x) * (g.w - g.y);
        slab[j]  = labels[j];
    }
    __syncthreads();

    int base = blockIdx.x * (BLOCK * APT);

    unsigned idx[APT];
    bool     act[APT];
    float4   a[APT];
    float    area[APT];
    // per-anchor argmax state (axis=1), division-free: best (inter, den) + j
    float    binter[APT], bden[APT];
    int      bj[APT];

    #pragma unroll
    for (int k = 0; k < APT; ++k) {
        idx[k]  = (unsigned)(base + k * BLOCK + tid);
        act[k]  = (idx[k] < (unsigned)N);
        a[k]    = anchors[act[k] ? idx[k] : 0];
        area[k] = (a[k].z - a[k].x) * (a[k].w - a[k].y);
        binter[k] = -1.0f;   // j=0 always wins the first compare (den > 0)
        bden[k]   = 1.0f;
        bj[k]     = 0;
    }

    // Global high-water mark: hi word of g_gt_key[j] = best iou bits so far.
    // __ldcg (L2) sees atomic updates from other blocks; staleness only means
    // extra tournaments, never missed winners (atomicMax is the authority).
    const unsigned* gk_hi = ((const unsigned*)g_gt_key) + 1;  // stride 2

    for (int j = 0; j < M; ++j) {
        float4 g  = sgt[j];
        float  sa = sarea[j];

        // lane's candidate for GT j: best over its APT anchors
        float    ti = 0.0f, td = 1.0f;
        unsigned tx = 0xFFFFFFFFu;

        #pragma unroll
        for (int k = 0; k < APT; ++k) {
            float lx = fmaxf(a[k].x, g.x);
            float ly = fmaxf(a[k].y, g.y);
            float rx = fminf(a[k].z, g.z);
            float ry = fminf(a[k].w, g.w);
            float w  = fmaxf(rx - lx, 0.0f);
            float h  = fmaxf(ry - ly, 0.0f);
            float inter    = w * h;
            float area_sum = area[k] + sa;      // reference eval order
            float den      = area_sum - inter;  // > 0 always
            if (!act[k]) inter = 0.0f;

            // per-anchor argmax (axis=1), strict '>' keeps first j
            if (inter * bden[k] > binter[k] * den) {
                binter[k] = inter; bden[k] = den; bj[k] = j;
            }
            // lane candidate (axis=0), strict '>' prefers smaller k = smaller idx
            if (inter * td > ti * den) {
                ti = inter; td = den; tx = idx[k];
            }
        }

        // Gate: can any lane possibly beat the global best for this GT?
        // iou >= hc  <=>  inter*(1+hc) >= hc*area_sum   (division-free).
        // Conservative margin => may admit losers, never filters a winner.
        float hi = __uint_as_float(__ldcg(gk_hi + 2 * j));
        float hc = hi * 0.9999f;
        bool  cand = (ti > 0.0f) && (fmaf(hc, ti, ti) >= hc * (ti + td));
        unsigned bal = __ballot_sync(0xFFFFFFFFu, cand);
        if (bal == 0u) continue;   // steady state after warm-up

        // warp tournament, division-free cross-mult compare; symmetric
        // products + idx tie-break => all lanes converge to one winner.
        #pragma unroll
        for (int off = 16; off; off >>= 1) {
            float    oi = __shfl_xor_sync(0xFFFFFFFFu, ti, off);
            float    od = __shfl_xor_sync(0xFFFFFFFFu, td, off);
            unsigned ox = __shfl_xor_sync(0xFFFFFFFFu, tx, off);
            float p_o = oi * td;
            float p_m = ti * od;
            bool take = (p_o > p_m) || ((p_o == p_m) && (ox < tx));
            if (take) { ti = oi; td = od; tx = ox; }
        }

        if (lane == 0 && ti > 0.0f) {
            float iou = __fdiv_rn(ti, td);     // exact, reference-rounded
            atomicMax(&g_gt_key[j], pack_key(iou, tx));
        }
    }

    bool al4 = (aligned4 != 0);
    #pragma unroll
    for (int k = 0; k < APT; ++k) {
        if (!act[k]) continue;
        float best = __fdiv_rn(binter[k], bden[k]);  // reference-rounded max IoU
        bool pos = (best >= 0.5f);
        bool neg = (best < 0.4f) && !pos;
        out[idx[k]] = (float)(pos ? slab[bj[k]] : (neg ? 0 : -1));
        encode_write(out, N, a[k], sgt[bj[k]], idx[k], pos, al4);
        out[5 * N + idx[k]] = pos ? 1.0f : 0.0f;
    }
}

// Force best-anchor-per-GT positive: one WARP per GT. Each lane scans 4 GT
// columns (j = lane*4..lane*4+3) of the winning anchor's IoU row,
// division-free; 5-step tournament (tie -> smaller j) finds that anchor's
// per-anchor argmax; lane 0 writes. Resets g_gt_key for the next replay.
// Several GTs sharing one best anchor write identical values => deterministic.
__global__ void fix_kernel(const float4* __restrict__ anchors,
                           const float4* __restrict__ gts,
                           const int* __restrict__ labels,
                           float* __restrict__ out,
                           int N, int M, int aligned4)
{
    int warp = threadIdx.x >> 5;
    int lane = threadIdx.x & 31;
    int gt   = blockIdx.x * 4 + warp;
    if (gt >= M_GT) return;

    unsigned long long key = (gt < M_GT) ? g_gt_key[gt] : 0ULL;
    if (lane == 0) g_gt_key[gt] = 0ULL;       // restore invariant
    if (gt >= M) return;

    // key==0 => all ious for this GT were 0; jnp.argmax of all-zero col = 0
    int aidx = (key == 0ULL) ? 0
             : (int)(0xFFFFFFFFu - (unsigned)(key & 0xFFFFFFFFULL));
    if (aidx < 0 || aidx >= N) return;

    float4 a = anchors[aidx];                 // broadcast load, all lanes same
    float area_a = (a.z - a.x) * (a.w - a.y);

    // lane scans j = lane*4 .. lane*4+3 (ascending => strict '>' keeps first j)
    float bi = -1.0f, bd = 1.0f;
    int   bj = lane * 4;
    #pragma unroll
    for (int kk = 0; kk < 4; ++kk) {
        int j = lane * 4 + kk;
        if (j >= M) break;
        float4 g = gts[j];
        float sa = (g.z - g.x) * (g.w - g.y);
        float lx = fmaxf(a.x, g.x);
        float ly = fmaxf(a.y, g.y);
        float rx = fminf(a.z, g.z);
        float ry = fminf(a.w, g.w);
        float w  = fmaxf(rx - lx, 0.0f);
        float h  = fmaxf(ry - ly, 0.0f);
        float inter = w * h;
        float den   = (area_a + sa) - inter;
        if (inter * bd > bi * den) { bi = inter; bd = den; bj = j; }
    }
    // lanes whose first j >= M keep bi=-1 (never win; M>=1 so lane 0 valid)

    #pragma unroll
    for (int off = 16; off; off >>= 1) {
        float oi = __shfl_xor_sync(0xFFFFFFFFu, bi, off);
        float od = __shfl_xor_sync(0xFFFFFFFFu, bd, off);
        int   oj = __shfl_xor_sync(0xFFFFFFFFu, bj, off);
        float p_o = oi * bd;
        float p_m = bi * od;
        bool take = (p_o > p_m) || ((p_o == p_m) && (oj < bj));
        if (take) { bi = oi; bd = od; bj = oj; }
    }

    if (lane == 0) {
        float4 g = gts[bj];
        out[aidx] = (float)labels[bj];
        encode_write(out, N, a, g, aidx, true, aligned4 != 0);
        out[5 * N + aidx] = 1.0f;
    }
}

extern "C" void kernel_launch(void* const* d_in, const int* in_sizes, int n_in,
                              void* d_out, int out_size)
{
    const float4* anchors = (const float4*)d_in[0];
    const float4* gts     = (const float4*)d_in[1];
    const int*    labels  = (const int*)d_in[2];
    float*        out     = (float*)d_out;

    int N = in_sizes[0] / 4;
    int M = in_sizes[2];
    if (M > M_GT) M = M_GT;
    int aligned4 = ((N & 3) == 0) ? 1 : 0;

    int blocks = (N + BLOCK * APT - 1) / (BLOCK * APT);
    match_kernel<<<blocks, BLOCK>>>(anchors, gts, labels, out, N, M, aligned4);
    fix_kernel<<<M_GT / 4, 128>>>(anchors, gts, labels, out, N, M, aligned4);
}

// round 15
// speedup vs baseline: 2.7417x; 2.0622x over previous
#include <cuda_runtime.h>
#include <math.h>

#define M_GT  128
#define BLOCK 128
#define APT   4            // anchors per thread (rotate around the warp)
#define GPL   4            // GTs per lane (32 lanes * 4 = 128 GT columns)

// Per-GT best-anchor key: (iou_bits << 32) | (0xFFFFFFFF - anchor_idx).
// IoU >= 0 so float bits are order-preserving under unsigned max; ~idx makes
// the smaller anchor index win ties (matches jnp.argmax axis=0 tie-break).
// Zero-initialized at module load; fix_kernel re-zeros after each use, so
// every launch / graph replay starts from 0.
__device__ unsigned long long g_gt_key[M_GT];

__device__ __forceinline__ unsigned long long pack_key(float iou, unsigned idx) {
    return (((unsigned long long)__float_as_uint(iou)) << 32) |
           (unsigned long long)(0xFFFFFFFFu - idx);
}

__device__ __forceinline__ void encode_write(float* __restrict__ out, int N,
                                             float4 a, float4 g, int i,
                                             bool pos, bool aligned4) {
    float dx = 0.0f, dy = 0.0f, dw = 0.0f, dh = 0.0f;
    if (pos) {   // skip divisions + logf (MUFU) for the ~95% non-positive anchors
        const float EPS = 1.1920929e-07f;  // jnp.finfo(float32).eps
        float ax = (a.x + a.z) * 0.5f;
        float ay = (a.y + a.w) * 0.5f;
        float aw = fmaxf(a.z - a.x, EPS);
        float ah = fmaxf(a.w - a.y, EPS);
        float gx = (g.x + g.z) * 0.5f;
        float gy = (g.y + g.w) * 0.5f;
        dx = (gx - ax) / aw;
        dy = (gy - ay) / ah;
        dw = logf((g.z - g.x) / aw);
        dh = logf((g.w - g.y) / ah);
    }
    if (aligned4) {
        ((float4*)(out + N))[i] = make_float4(dx, dy, dw, dh);
    } else {
        float* r = out + N + 4 * i;
        r[0] = dx; r[1] = dy; r[2] = dw; r[3] = dh;
    }
}

__global__ void __launch_bounds__(BLOCK)
match_kernel(const float4* __restrict__ anchors,
             const float4* __restrict__ gts,
             const int* __restrict__ labels,
             float* __restrict__ out,
             int N, int M, int aligned4)
{
    __shared__ float4 sgt[M_GT];
    __shared__ int    slab[M_GT];

    int tid  = threadIdx.x;
    int lane = tid & 31;
    int warp = tid >> 5;
    for (int j = tid; j < M; j += BLOCK) {
        sgt[j]  = gts[j];
        slab[j] = labels[j];
    }
    __syncthreads();

    // ---- GT registers: lane owns columns j = 4*lane .. 4*lane+3 ----
    int    jbase = lane * GPL;
    float4 gq[GPL];
    float  gsa[GPL];
    float  gbi[GPL], gbd[GPL];     // per-GT best (inter, den), block-local
    unsigned gbx[GPL];             // per-GT best anchor idx
    #pragma unroll
    for (int kk = 0; kk < GPL; ++kk) {
        int j = jbase + kk;
        if (j < M) {
            float4 g = sgt[j];
            gq[kk]  = g;
            gsa[kk] = (g.z - g.x) * (g.w - g.y);
        } else {
            gq[kk]  = make_float4(3e38f, 3e38f, 3e38f, 3e38f);  // inter -> 0
            gsa[kk] = 1.0f;                                     // den > 0
        }
        gbi[kk] = 0.0f; gbd[kk] = 1.0f; gbx[kk] = 0xFFFFFFFFu;
    }

    // ---- Anchor payload: travels around the warp with its argmax state ----
    unsigned wbase = (unsigned)(blockIdx.x * (BLOCK * APT) + warp * 32);
    float ax[APT], ay[APT], az[APT], aw2[APT];
    float abi[APT], abd[APT];      // per-anchor best (inter, den)
    int   abj[APT];                // per-anchor best GT column
    #pragma unroll
    for (int k = 0; k < APT; ++k) {
        unsigned i0 = wbase + (unsigned)(k * BLOCK) + (unsigned)lane;
        if (i0 < (unsigned)N) {
            float4 t = anchors[i0];
            ax[k] = t.x; ay[k] = t.y; az[k] = t.z; aw2[k] = t.w;
        } else {                   // degenerate: inter = 0, area = 0
            ax[k] = ay[k] = az[k] = aw2[k] = 3e38f;
        }
        abi[k] = 0.0f; abd[k] = 1.0f; abj[k] = 0x7FFFFFFF;
    }

    // ---- Systolic loop: registers only. 32 compute steps, 31 rotations ----
    int src = (lane + 1) & 31;
    #pragma unroll 1
    for (int r = 0; r < 32; ++r) {
        #pragma unroll
        for (int k = 0; k < APT; ++k) {
            float area_a = (az[k] - ax[k]) * (aw2[k] - ay[k]);
            unsigned aidx = wbase + (unsigned)(k * BLOCK)
                          + (unsigned)((lane + r) & 31);
            #pragma unroll
            for (int kk = 0; kk < GPL; ++kk) {
                int j = jbase + kk;
                float lx = fmaxf(ax[k],  gq[kk].x);
                float ly = fmaxf(ay[k],  gq[kk].y);
                float rx = fminf(az[k],  gq[kk].z);
                float ry = fminf(aw2[k], gq[kk].w);
                float w  = fmaxf(rx - lx, 0.0f);
                float h  = fmaxf(ry - ly, 0.0f);
                float inter = w * h;
                float den   = (area_a + gsa[kk]) - inter;   // > 0

                // per-anchor argmax (axis=1), division-free; exact-equal
                // rationals give bit-equal cross products -> tie by smaller j
                float pn = inter * abd[k];
                float pb = abi[k] * den;
                bool tA = (pn > pb) || ((pn == pb) && (j < abj[k]));
                if ((j < M) && tA) { abi[k] = inter; abd[k] = den; abj[k] = j; }

                // per-GT argmax (axis=0), tie -> smaller anchor idx
                float qn = inter * gbd[kk];
                float qb = gbi[kk] * den;
                bool tG = (qn > qb) || ((qn == qb) && (aidx < gbx[kk]));
                if ((inter > 0.0f) && tG) {
                    gbi[kk] = inter; gbd[kk] = den; gbx[kk] = aidx;
                }
            }
        }
        if (r < 31) {
            #pragma unroll
            for (int k = 0; k < APT; ++k) {
                ax[k]  = __shfl_sync(0xFFFFFFFFu, ax[k],  src);
                ay[k]  = __shfl_sync(0xFFFFFFFFu, ay[k],  src);
                az[k]  = __shfl_sync(0xFFFFFFFFu, az[k],  src);
                aw2[k] = __shfl_sync(0xFFFFFFFFu, aw2[k], src);
                abi[k] = __shfl_sync(0xFFFFFFFFu, abi[k], src);
                abd[k] = __shfl_sync(0xFFFFFFFFu, abd[k], src);
                abj[k] = __shfl_sync(0xFFFFFFFFu, abj[k], src);
            }
        }
    }

    // ---- per-GT epilogue: <=4 gated atomics per lane, off the hot loop ----
    #pragma unroll
    for (int kk = 0; kk < GPL; ++kk) {
        int j = jbase + kk;
        if (j < M && gbi[kk] > 0.0f) {
            // racy global high-water check; cold (hi=0) passes, warm skips.
            // Conservative margin: may admit losers, never filters a winner;
            // atomicMax stays the authority.
            float hi = __uint_as_float(__ldcg(((const unsigned*)&g_gt_key[j]) + 1));
            float hc = hi * 0.9999f;
            if (fmaf(hc, gbi[kk], gbi[kk]) >= hc * (gbi[kk] + gbd[kk])) {
                float iou = __fdiv_rn(gbi[kk], gbd[kk]);  // reference-rounded
                atomicMax(&g_gt_key[j], pack_key(iou, gbx[kk]));
            }
        }
    }

    // ---- per-anchor epilogue: anchors sit at rotation r=31 position ----
    bool al4 = (aligned4 != 0);
    #pragma unroll
    for (int k = 0; k < APT; ++k) {
        unsigned i = wbase + (unsigned)(k * BLOCK) + (unsigned)((lane + 31) & 31);
        if (i >= (unsigned)N) continue;
        float best = __fdiv_rn(abi[k], abd[k]);   // reference-rounded max IoU
        bool pos = (best >= 0.5f);
        bool neg = (best < 0.4f) && !pos;
        int  bj  = abj[k];
        out[i] = (float)(pos ? slab[bj] : (neg ? 0 : -1));
        float4 abox = make_float4(ax[k], ay[k], az[k], aw2[k]);
        encode_write(out, N, abox, sgt[bj], (int)i, pos, al4);
        out[5 * N + i] = pos ? 1.0f : 0.0f;
    }
}

// Force best-anchor-per-GT positive: one WARP per GT. Lane scans 4 GT
// columns of the winning anchor's IoU row division-free; 5-step tournament
// (tie -> smaller j). Resets g_gt_key for the next replay. GTs sharing one
// best anchor write identical values => deterministic.
__global__ void fix_kernel(const float4* __restrict__ anchors,
                           const float4* __restrict__ gts,
                           const int* __restrict__ labels,
                           float* __restrict__ out,
                           int N, int M, int aligned4)
{
    int warp = threadIdx.x >> 5;
    int lane = threadIdx.x & 31;
    int gt   = blockIdx.x * 4 + warp;
    if (gt >= M_GT) return;

    unsigned long long key = g_gt_key[gt];
    if (lane == 0) g_gt_key[gt] = 0ULL;       // restore invariant
    if (gt >= M) return;

    // key==0 => all ious for this GT were 0; jnp.argmax of all-zero col = 0
    int aidx = (key == 0ULL) ? 0
             : (int)(0xFFFFFFFFu - (unsigned)(key & 0xFFFFFFFFULL));
    if (aidx < 0 || aidx >= N) return;

    float4 a = anchors[aidx];                 // broadcast load
    float area_a = (a.z - a.x) * (a.w - a.y);

    float bi = -1.0f, bd = 1.0f;
    int   bj = lane * 4;
    #pragma unroll
    for (int kk = 0; kk < 4; ++kk) {
        int j = lane * 4 + kk;
        if (j >= M) break;
        float4 g = gts[j];
        float sa = (g.z - g.x) * (g.w - g.y);
        float lx = fmaxf(a.x, g.x);
        float ly = fmaxf(a.y, g.y);
        float rx = fminf(a.z, g.z);
        float ry = fminf(a.w, g.w);
        float w  = fmaxf(rx - lx, 0.0f);
        float h  = fmaxf(ry - ly, 0.0f);
        float inter = w * h;
        float den   = (area_a + sa) - inter;
        if (inter * bd > bi * den) { bi = inter; bd = den; bj = j; }
    }

    #pragma unroll
    for (int off = 16; off; off >>= 1) {
        float oi = __shfl_xor_sync(0xFFFFFFFFu, bi, off);
        float od = __shfl_xor_sync(0xFFFFFFFFu, bd, off);
        int   oj = __shfl_xor_sync(0xFFFFFFFFu, bj, off);
        float p_o = oi * bd;
        float p_m = bi * od;
        bool take = (p_o > p_m) || ((p_o == p_m) && (oj < bj));
        if (take) { bi = oi; bd = od; bj = oj; }
    }

    if (lane == 0) {
        float4 g = gts[bj];
        out[aidx] = (float)labels[bj];
        encode_write(out, N, a, g, aidx, true, aligned4 != 0);
        out[5 * N + aidx] = 1.0f;
    }
}

extern "C" void kernel_launch(void* const* d_in, const int* in_sizes, int n_in,
                              void* d_out, int out_size)
{
    const float4* anchors = (const float4*)d_in[0];
    const float4* gts     = (const float4*)d_in[1];
    const int*    labels  = (const int*)d_in[2];
    float*        out     = (float*)d_out;

    int N = in_sizes[0] / 4;
    int M = in_sizes[2];
    if (M > M_GT) M = M_GT;
    int aligned4 = ((N & 3) == 0) ? 1 : 0;

    int blocks = (N + BLOCK * APT - 1) / (BLOCK * APT);
    match_kernel<<<blocks, BLOCK>>>(anchors, gts, labels, out, N, M, aligned4);
    fix_kernel<<<M_GT / 4, 128>>>(anchors, gts, labels, out, N, M, aligned4);
}

// round 16
// speedup vs baseline: 3.1523x; 1.1498x over previous
#include <cuda_runtime.h>
#include <math.h>

#define M_GT   128
#define BLOCK  256
#define WARPS  (BLOCK / 32)
#define APT    2             // anchors per thread (rotate around the warp)
#define GPL    4             // GTs per lane (32 lanes * 4 = 128 GT columns)
#define APW    (32 * APT)    // anchors per warp

// Per-GT best-anchor key: (iou_bits << 32) | (0xFFFFFFFF - anchor_idx).
// IoU >= 0 so float bits are order-preserving under unsigned max; ~idx makes
// the smaller anchor index win ties (matches jnp.argmax axis=0 tie-break).
// Zero-initialized at module load; fix_kernel re-zeros after each use, so
// every launch / graph replay starts from 0.
__device__ unsigned long long g_gt_key[M_GT];

__device__ __forceinline__ unsigned long long pack_key(float iou, unsigned idx) {
    return (((unsigned long long)__float_as_uint(iou)) << 32) |
           (unsigned long long)(0xFFFFFFFFu - idx);
}

__device__ __forceinline__ void encode_write(float* __restrict__ out, int N,
                                             float4 a, float4 g, int i,
                                             bool pos, bool aligned4) {
    float dx = 0.0f, dy = 0.0f, dw = 0.0f, dh = 0.0f;
    if (pos) {   // skip divisions + logf (MUFU) for ~95% non-positive anchors
        const float EPS = 1.1920929e-07f;  // jnp.finfo(float32).eps
        float ax = (a.x + a.z) * 0.5f;
        float ay = (a.y + a.w) * 0.5f;
        float aw = fmaxf(a.z - a.x, EPS);
        float ah = fmaxf(a.w - a.y, EPS);
        float gx = (g.x + g.z) * 0.5f;
        float gy = (g.y + g.w) * 0.5f;
        dx = (gx - ax) / aw;
        dy = (gy - ay) / ah;
        dw = logf((g.z - g.x) / aw);
        dh = logf((g.w - g.y) / ah);
    }
    if (aligned4) {
        ((float4*)(out + N))[i] = make_float4(dx, dy, dw, dh);
    } else {
        float* r = out + N + 4 * i;
        r[0] = dx; r[1] = dy; r[2] = dw; r[3] = dh;
    }
}

__global__ void __launch_bounds__(BLOCK)
match_kernel(const float4* __restrict__ anchors,
             const float4* __restrict__ gts,
             const int* __restrict__ labels,
             float* __restrict__ out,
             int N, int M, int aligned4)
{
    __shared__ float4 sgt[M_GT];
    __shared__ int    slab[M_GT];

    int tid  = threadIdx.x;
    int lane = tid & 31;
    int warp = tid >> 5;
    for (int j = tid; j < M; j += BLOCK) {
        sgt[j]  = gts[j];
        slab[j] = labels[j];
    }
    __syncthreads();

    // ---- GT registers: lane owns columns j = 4*lane .. 4*lane+3 ----
    int    jbase = lane * GPL;
    float4 gq[GPL];
    float  gsa[GPL];
    float  gbi[GPL], gbd[GPL];     // per-GT best (inter, den), warp-local
    unsigned gbx[GPL];             // per-GT best anchor idx
    #pragma unroll
    for (int kk = 0; kk < GPL; ++kk) {
        int j = jbase + kk;
        if (j < M) {
            float4 g = sgt[j];
            gq[kk]  = g;
            gsa[kk] = (g.z - g.x) * (g.w - g.y);
        } else {
            gq[kk]  = make_float4(3e38f, 3e38f, 3e38f, 3e38f);  // inter -> 0
            gsa[kk] = 1.0f;                                     // den > 0
        }
        gbi[kk] = 0.0f; gbd[kk] = 1.0f; gbx[kk] = 0xFFFFFFFFu;
    }

    // ---- Anchor payload: travels around the warp with its argmax state ----
    unsigned wbase = (unsigned)((blockIdx.x * WARPS + warp) * APW);
    float ax[APT], ay[APT], az[APT], aw2[APT];
    float abi[APT], abd[APT];      // per-anchor best (inter, den)
    int   abj[APT];                // per-anchor best GT column
    #pragma unroll
    for (int k = 0; k < APT; ++k) {
        unsigned i0 = wbase + (unsigned)(k * 32) + (unsigned)lane;
        if (i0 < (unsigned)N) {
            float4 t = anchors[i0];
            ax[k] = t.x; ay[k] = t.y; az[k] = t.z; aw2[k] = t.w;
        } else {                   // degenerate: inter = 0, area = 0
            ax[k] = ay[k] = az[k] = aw2[k] = 3e38f;
        }
        abi[k] = 0.0f; abd[k] = 1.0f; abj[k] = 0x7FFFFFFF;
    }

    // ---- Systolic loop: registers only. 32 compute steps, 31 rotations ----
    int src = (lane + 1) & 31;
    #pragma unroll 1
    for (int r = 0; r < 32; ++r) {
        #pragma unroll
        for (int k = 0; k < APT; ++k) {
            float area_a = (az[k] - ax[k]) * (aw2[k] - ay[k]);
            unsigned aidx = wbase + (unsigned)(k * 32)
                          + (unsigned)((lane + r) & 31);
            #pragma unroll
            for (int kk = 0; kk < GPL; ++kk) {
                int j = jbase + kk;
                float lx = fmaxf(ax[k],  gq[kk].x);
                float ly = fmaxf(ay[k],  gq[kk].y);
                float rx = fminf(az[k],  gq[kk].z);
                float ry = fminf(aw2[k], gq[kk].w);
                float w  = fmaxf(rx - lx, 0.0f);
                float h  = fmaxf(ry - ly, 0.0f);
                float inter = w * h;
                float den   = (area_a + gsa[kk]) - inter;   // > 0

                // per-anchor argmax (axis=1), division-free; exact-equal
                // rationals give bit-equal cross products -> tie by smaller j
                float pn = inter * abd[k];
                float pb = abi[k] * den;
                bool tA = (pn > pb) || ((pn == pb) && (j < abj[k]));
                if ((j < M) && tA) { abi[k] = inter; abd[k] = den; abj[k] = j; }

                // per-GT argmax (axis=0), tie -> smaller anchor idx.
                // Zero-iou candidates can only touch gbx while gbi stays 0;
                // epilogue gates on gbi>0 and fix handles the all-zero case.
                float qn = inter * gbd[kk];
                float qb = gbi[kk] * den;
                bool tG = (qn > qb) || ((qn == qb) && (aidx < gbx[kk]));
                if (tG) { gbi[kk] = inter; gbd[kk] = den; gbx[kk] = aidx; }
            }
        }
        if (r < 31) {
            #pragma unroll
            for (int k = 0; k < APT; ++k) {
                ax[k]  = __shfl_sync(0xFFFFFFFFu, ax[k],  src);
                ay[k]  = __shfl_sync(0xFFFFFFFFu, ay[k],  src);
                az[k]  = __shfl_sync(0xFFFFFFFFu, az[k],  src);
                aw2[k] = __shfl_sync(0xFFFFFFFFu, aw2[k], src);
                abi[k] = __shfl_sync(0xFFFFFFFFu, abi[k], src);
                abd[k] = __shfl_sync(0xFFFFFFFFu, abd[k], src);
                abj[k] = __shfl_sync(0xFFFFFFFFu, abj[k], src);
            }
        }
    }

    // ---- per-GT epilogue: <=4 gated atomics per lane, off the hot loop ----
    #pragma unroll
    for (int kk = 0; kk < GPL; ++kk) {
        int j = jbase + kk;
        if (j < M && gbi[kk] > 0.0f) {
            // racy global high-water check; cold (hi=0) passes, warm skips.
            // Conservative margin: may admit losers, never filters a winner;
            // atomicMax stays the authority.
            float hi = __uint_as_float(__ldcg(((const unsigned*)&g_gt_key[j]) + 1));
            float hc = hi * 0.9999f;
            if (fmaf(hc, gbi[kk], gbi[kk]) >= hc * (gbi[kk] + gbd[kk])) {
                float iou = __fdiv_rn(gbi[kk], gbd[kk]);  // reference-rounded
                atomicMax(&g_gt_key[j], pack_key(iou, gbx[kk]));
            }
        }
    }

    // ---- per-anchor epilogue: anchors sit at rotation r=31 position ----
    bool al4 = (aligned4 != 0);
    #pragma unroll
    for (int k = 0; k < APT; ++k) {
        unsigned i = wbase + (unsigned)(k * 32) + (unsigned)((lane + 31) & 31);
        if (i >= (unsigned)N) continue;
        float best = __fdiv_rn(abi[k], abd[k]);   // reference-rounded max IoU
        bool pos = (best >= 0.5f);
        bool neg = (best < 0.4f) && !pos;
        int  bj  = abj[k];
        out[i] = (float)(pos ? slab[bj] : (neg ? 0 : -1));
        float4 abox = make_float4(ax[k], ay[k], az[k], aw2[k]);
        encode_write(out, N, abox, sgt[bj], (int)i, pos, al4);
        out[5 * N + i] = pos ? 1.0f : 0.0f;
    }
}

// Force best-anchor-per-GT positive: one WARP per GT. Lane scans 4 GT
// columns of the winning anchor's IoU row division-free; 5-step tournament
// (tie -> smaller j). Resets g_gt_key for the next replay. GTs sharing one
// best anchor write identical values => deterministic.
__global__ void fix_kernel(const float4* __restrict__ anchors,
                           const float4* __restrict__ gts,
                           const int* __restrict__ labels,
                           float* __restrict__ out,
                           int N, int M, int aligned4)
{
    int warp = threadIdx.x >> 5;
    int lane = threadIdx.x & 31;
    int gt   = blockIdx.x * 4 + warp;
    if (gt >= M_GT) return;

    unsigned long long key = g_gt_key[gt];
    if (lane == 0) g_gt_key[gt] = 0ULL;       // restore invariant
    if (gt >= M) return;

    // key==0 => all ious for this GT were 0; jnp.argmax of all-zero col = 0
    int aidx = (key == 0ULL) ? 0
             : (int)(0xFFFFFFFFu - (unsigned)(key & 0xFFFFFFFFULL));
    if (aidx < 0 || aidx >= N) return;

    float4 a = anchors[aidx];                 // broadcast load
    float area_a = (a.z - a.x) * (a.w - a.y);

    float bi = -1.0f, bd = 1.0f;
    int   bj = lane * 4;
    #pragma unroll
    for (int kk = 0; kk < 4; ++kk) {
        int j = lane * 4 + kk;
        if (j >= M) break;
        float4 g = gts[j];
        float sa = (g.z - g.x) * (g.w - g.y);
        float lx = fmaxf(a.x, g.x);
        float ly = fmaxf(a.y, g.y);
        float rx = fminf(a.z, g.z);
        float ry = fminf(a.w, g.w);
        float w  = fmaxf(rx - lx, 0.0f);
        float h  = fmaxf(ry - ly, 0.0f);
        float inter = w * h;
        float den   = (area_a + sa) - inter;
        if (inter * bd > bi * den) { bi = inter; bd = den; bj = j; }
    }

    #pragma unroll
    for (int off = 16; off; off >>= 1) {
        float oi = __shfl_xor_sync(0xFFFFFFFFu, bi, off);
        float od = __shfl_xor_sync(0xFFFFFFFFu, bd, off);
        int   oj = __shfl_xor_sync(0xFFFFFFFFu, bj, off);
        float p_o = oi * bd;
        float p_m = bi * od;
        bool take = (p_o > p_m) || ((p_o == p_m) && (oj < bj));
        if (take) { bi = oi; bd = od; bj = oj; }
    }

    if (lane == 0) {
        float4 g = gts[bj];
        out[aidx] = (float)labels[bj];
        encode_write(out, N, a, g, aidx, true, aligned4 != 0);
        out[5 * N + aidx] = 1.0f;
    }
}

extern "C" void kernel_launch(void* const* d_in, const int* in_sizes, int n_in,
                              void* d_out, int out_size)
{
    const float4* anchors = (const float4*)d_in[0];
    const float4* gts     = (const float4*)d_in[1];
    const int*    labels  = (const int*)d_in[2];
    float*        out     = (float*)d_out;

    int N = in_sizes[0] / 4;
    int M = in_sizes[2];
    if (M > M_GT) M = M_GT;
    int aligned4 = ((N & 3) == 0) ? 1 : 0;

    int per_block = BLOCK * APT;   // 512 anchors per block
    int blocks = (N + per_block - 1) / per_block;
    match_kernel<<<blocks, BLOCK>>>(anchors, gts, labels, out, N, M, aligned4);
    fix_kernel<<<M_GT / 4, 128>>>(anchors, gts, labels, out, N, M, aligned4);
}